// round 3
// baseline (speedup 1.0000x reference)
#include <cuda_runtime.h>
#include <cstdint>
#include <cstddef>

#define D_MODEL 1024
#define NH      16
#define DK      64
#define BATCH   2
#define SEQ     2048
#define M_ROWS  (BATCH * SEQ)                 // 4096
#define OUT_ELEMS ((size_t)M_ROWS * D_MODEL)  // 4194304

// Scratch (allocation-free rule: __device__ globals)
__device__ float g_q[BATCH * NH * SEQ * DK];   // [b,h,s,d]
__device__ float g_k[BATCH * NH * SEQ * DK];   // [b,h,d,s]  (transposed per head)
__device__ float g_v[BATCH * NH * SEQ * DK];   // [b,h,s,d]
__device__ float g_ctx[M_ROWS * D_MODEL];      // [b,s,D]

// ---------------------------------------------------------------------------
// SGEMM: C = A[M=4096,K=1024] @ B[K=1024,N=1024] + bias, 128x128x8 tiles.
// mode 0: dst head-split [b,h,s,d]   (Q, V)
// mode 1: dst head-split transposed [b,h,d,s]   (K)
// mode 2: dst plain row-major [m, n]   (final out)
// ---------------------------------------------------------------------------
__global__ __launch_bounds__(256) void sgemm_bias(
    const float* __restrict__ A, const float* __restrict__ B,
    const float* __restrict__ bias, float* __restrict__ C, int mode)
{
    __shared__ float As[8][128];   // [k][m]
    __shared__ float Bs[8][128];   // [k][n]
    const int K = 1024, N = 1024;
    int tid = threadIdx.x;
    int bm = blockIdx.y * 128;
    int bn = blockIdx.x * 128;
    int tx = tid & 15, ty = tid >> 4;

    float acc[8][8];
#pragma unroll
    for (int i = 0; i < 8; i++)
#pragma unroll
        for (int j = 0; j < 8; j++) acc[i][j] = 0.f;

    int aRow = tid >> 1;
    int aCol = (tid & 1) * 4;
    int bRow = tid >> 5;
    int bCol = (tid & 31) * 4;
    const float* Aptr = A + (size_t)(bm + aRow) * K + aCol;
    const float* Bptr = B + (size_t)bRow * N + bn + bCol;

    for (int k0 = 0; k0 < K; k0 += 8) {
        float4 av = *(const float4*)(Aptr + k0);
        As[aCol + 0][aRow] = av.x;
        As[aCol + 1][aRow] = av.y;
        As[aCol + 2][aRow] = av.z;
        As[aCol + 3][aRow] = av.w;
        float4 bv = *(const float4*)(Bptr + (size_t)k0 * N);
        *(float4*)&Bs[bRow][bCol] = bv;
        __syncthreads();
#pragma unroll
        for (int kk = 0; kk < 8; kk++) {
            float ra[8], rb[8];
            *(float4*)&ra[0] = *(const float4*)&As[kk][ty * 8];
            *(float4*)&ra[4] = *(const float4*)&As[kk][ty * 8 + 4];
            *(float4*)&rb[0] = *(const float4*)&Bs[kk][tx * 8];
            *(float4*)&rb[4] = *(const float4*)&Bs[kk][tx * 8 + 4];
#pragma unroll
            for (int i = 0; i < 8; i++)
#pragma unroll
                for (int j = 0; j < 8; j++)
                    acc[i][j] = fmaf(ra[i], rb[j], acc[i][j]);
        }
        __syncthreads();
    }

    if (mode == 2) {
#pragma unroll
        for (int i = 0; i < 8; i++) {
            int m = bm + ty * 8 + i;
            float* crow = C + (size_t)m * N + bn + tx * 8;
#pragma unroll
            for (int j = 0; j < 8; j++)
                crow[j] = acc[i][j] + bias[bn + tx * 8 + j];
        }
    } else if (mode == 0) {
#pragma unroll
        for (int i = 0; i < 8; i++) {
            int m = bm + ty * 8 + i;
            int bb = m >> 11, s = m & 2047;
#pragma unroll
            for (int j = 0; j < 8; j++) {
                int n = bn + tx * 8 + j;
                int h = n >> 6, d = n & 63;
                C[(((size_t)(bb * NH + h)) * SEQ + s) * DK + d] = acc[i][j] + bias[n];
            }
        }
    } else {  // mode 1: K transposed per head
#pragma unroll
        for (int j = 0; j < 8; j++) {
            int n = bn + tx * 8 + j;
            int h = n >> 6, d = n & 63;
            float bval = bias[n];
#pragma unroll
            for (int i = 0; i < 8; i++) {
                int m = bm + ty * 8 + i;
                int bb = m >> 11, s = m & 2047;
                C[(((size_t)(bb * NH + h)) * DK + d) * SEQ + s] = acc[i][j] + bval;
            }
        }
    }
}

// ---------------------------------------------------------------------------
// Fused attention: per block = 16 query rows of one (b,h).
// Phase 1: scores (16x2048) into smem via tiled GEMM against K^T tiles.
// Phase 2: softmax rows in smem, write attn probs to gmem (once).
// Phase 3: ctx = P @ V with V tiles in smem.
// ---------------------------------------------------------------------------
#define SC_LD   2052            // 2052 % 32 == 4 -> no cross-row conflicts, fp4-aligned
#define QS_LD   68
#define KT_LD   260
#define KT_TILE 256
#define VT_TILE 128
#define SMEM_QS_OFF (16 * SC_LD)                 // 32832
#define SMEM_KV_OFF (SMEM_QS_OFF + 16 * QS_LD)   // 33920
#define ATTN_SMEM_FLOATS (SMEM_KV_OFF + 64 * KT_LD)  // + 16640 = 50560
#define ATTN_SMEM_BYTES  (ATTN_SMEM_FLOATS * 4)      // 202240 B

__global__ __launch_bounds__(256) void attn_kernel(
    const float* __restrict__ gq, const float* __restrict__ gkt,
    const float* __restrict__ gv, float* __restrict__ attn_out,
    float* __restrict__ ctx)
{
    extern __shared__ float sm[];
    float* sc = sm;
    float* Qs = sm + SMEM_QS_OFF;
    float* KV = sm + SMEM_KV_OFF;

    int tid = threadIdx.x;
    int bh = blockIdx.y;
    int b = bh >> 4, h = bh & 15;
    int q0 = blockIdx.x * 16;
    const float* Q  = gq  + (size_t)bh * SEQ * DK;
    const float* KT = gkt + (size_t)bh * SEQ * DK;   // [64][2048]
    const float* V  = gv  + (size_t)bh * SEQ * DK;   // [2048][64]

    // Load Q tile [16][64] -> Qs (row-major, padded)
    {
        int q = tid >> 4, d0 = (tid & 15) * 4;
        float4 v = *(const float4*)&Q[(size_t)(q0 + q) * DK + d0];
        *(float4*)&Qs[q * QS_LD + d0] = v;
    }
    __syncthreads();

    int qg = tid >> 6;   // 0..3  (4 q-rows each)
    int kg = tid & 63;   // 0..63 (4 k-cols each)

    // ===== Phase 1: scores =====
    for (int kt0 = 0; kt0 < SEQ; kt0 += KT_TILE) {
        // Fill K^T tile [64][256] -> KV[kk*260 + c]; contiguous, conflict-free
#pragma unroll
        for (int i = 0; i < 16; i++) {
            int flat = tid + i * 256;            // float4 index, 4096 total
            int kk = flat >> 6, c4 = (flat & 63) * 4;
            float4 v = *(const float4*)&KT[(size_t)kk * SEQ + kt0 + c4];
            *(float4*)&KV[kk * KT_LD + c4] = v;
        }
        __syncthreads();

        float acc[4][4];
#pragma unroll
        for (int i = 0; i < 4; i++)
#pragma unroll
            for (int j = 0; j < 4; j++) acc[i][j] = 0.f;

#pragma unroll
        for (int kk4 = 0; kk4 < 16; kk4++) {
            float4 kq[4];
            float  kvr[4][4];
#pragma unroll
            for (int u = 0; u < 4; u++) {
                kq[u] = *(const float4*)&Qs[(qg * 4 + u) * QS_LD + kk4 * 4];
                *(float4*)&kvr[u][0] = *(const float4*)&KV[(kk4 * 4 + u) * KT_LD + kg * 4];
            }
#pragma unroll
            for (int i = 0; i < 4; i++) {
                float qa0 = kq[i].x, qa1 = kq[i].y, qa2 = kq[i].z, qa3 = kq[i].w;
#pragma unroll
                for (int j = 0; j < 4; j++) {
                    acc[i][j] = fmaf(qa0, kvr[0][j], acc[i][j]);
                    acc[i][j] = fmaf(qa1, kvr[1][j], acc[i][j]);
                    acc[i][j] = fmaf(qa2, kvr[2][j], acc[i][j]);
                    acc[i][j] = fmaf(qa3, kvr[3][j], acc[i][j]);
                }
            }
        }
#pragma unroll
        for (int i = 0; i < 4; i++) {
            float4 o = make_float4(acc[i][0] * 0.125f, acc[i][1] * 0.125f,
                                   acc[i][2] * 0.125f, acc[i][3] * 0.125f);
            *(float4*)&sc[(qg * 4 + i) * SC_LD + kt0 + kg * 4] = o;
        }
        __syncthreads();
    }

    // ===== Phase 2: softmax + write attn =====
    {
        int w = tid >> 5, lane = tid & 31;
#pragma unroll 1
        for (int r = 0; r < 2; r++) {
            int q = w * 2 + r;
            float* row = sc + q * SC_LD;
            float mx = -3.0e38f;
            for (int i = lane * 4; i < SEQ; i += 128) {
                float4 v = *(const float4*)&row[i];
                mx = fmaxf(mx, fmaxf(fmaxf(v.x, v.y), fmaxf(v.z, v.w)));
            }
#pragma unroll
            for (int o = 16; o; o >>= 1)
                mx = fmaxf(mx, __shfl_xor_sync(0xffffffffu, mx, o));
            float sum = 0.f;
            for (int i = lane * 4; i < SEQ; i += 128) {
                float4 v = *(float4*)&row[i];
                v.x = __expf(v.x - mx); v.y = __expf(v.y - mx);
                v.z = __expf(v.z - mx); v.w = __expf(v.w - mx);
                *(float4*)&row[i] = v;
                sum += v.x + v.y + v.z + v.w;
            }
#pragma unroll
            for (int o = 16; o; o >>= 1)
                sum += __shfl_xor_sync(0xffffffffu, sum, o);
            float inv = 1.f / sum;
            float* gout = attn_out + ((size_t)bh * SEQ + q0 + q) * SEQ;
            for (int i = lane * 4; i < SEQ; i += 128) {
                float4 v = *(float4*)&row[i];
                v.x *= inv; v.y *= inv; v.z *= inv; v.w *= inv;
                *(float4*)&row[i] = v;
                *(float4*)&gout[i] = v;
            }
        }
    }
    __syncthreads();

    // ===== Phase 3: ctx = P @ V =====
    {
        int qq = tid >> 4;   // 0..15
        int dg = tid & 15;   // 0..15 -> 4 d each
        float a0 = 0.f, a1 = 0.f, a2 = 0.f, a3 = 0.f;
        for (int vt0 = 0; vt0 < SEQ; vt0 += VT_TILE) {
#pragma unroll
            for (int i = 0; i < 8; i++) {
                int flat = tid + i * 256;        // float4 idx, 2048 total
                int rrow = flat >> 4, c4 = (flat & 15) * 4;
                *(float4*)&KV[rrow * DK + c4] =
                    *(const float4*)&V[(size_t)(vt0 + rrow) * DK + c4];
            }
            __syncthreads();
            const float* prow = sc + qq * SC_LD + vt0;
#pragma unroll 4
            for (int kk = 0; kk < VT_TILE; kk += 4) {
                float4 p4 = *(const float4*)&prow[kk];
                float4 v0 = *(const float4*)&KV[(kk + 0) * DK + dg * 4];
                float4 v1 = *(const float4*)&KV[(kk + 1) * DK + dg * 4];
                float4 v2 = *(const float4*)&KV[(kk + 2) * DK + dg * 4];
                float4 v3 = *(const float4*)&KV[(kk + 3) * DK + dg * 4];
                a0 = fmaf(p4.x, v0.x, a0); a1 = fmaf(p4.x, v0.y, a1);
                a2 = fmaf(p4.x, v0.z, a2); a3 = fmaf(p4.x, v0.w, a3);
                a0 = fmaf(p4.y, v1.x, a0); a1 = fmaf(p4.y, v1.y, a1);
                a2 = fmaf(p4.y, v1.z, a2); a3 = fmaf(p4.y, v1.w, a3);
                a0 = fmaf(p4.z, v2.x, a0); a1 = fmaf(p4.z, v2.y, a1);
                a2 = fmaf(p4.z, v2.z, a2); a3 = fmaf(p4.z, v2.w, a3);
                a0 = fmaf(p4.w, v3.x, a0); a1 = fmaf(p4.w, v3.y, a1);
                a2 = fmaf(p4.w, v3.z, a2); a3 = fmaf(p4.w, v3.w, a3);
            }
            __syncthreads();
        }
        float4 o = make_float4(a0, a1, a2, a3);
        *(float4*)&ctx[((size_t)(b * SEQ) + q0 + qq) * D_MODEL + h * DK + dg * 4] = o;
    }
}

// ---------------------------------------------------------------------------
extern "C" void kernel_launch(void* const* d_in, const int* in_sizes, int n_in,
                              void* d_out, int out_size)
{
    const float* query = (const float*)d_in[0];
    const float* key   = (const float*)d_in[1];
    const float* value = (const float*)d_in[2];
    const float* Wq = (const float*)d_in[3];
    const float* bq = (const float*)d_in[4];
    const float* Wk = (const float*)d_in[5];
    const float* bk = (const float*)d_in[6];
    const float* Wv = (const float*)d_in[7];
    const float* bv = (const float*)d_in[8];
    const float* Wo = (const float*)d_in[9];
    const float* bo = (const float*)d_in[10];

    float* out  = (float*)d_out;
    float* attn = out + OUT_ELEMS;

    float *gq, *gk, *gv, *gctx;
    cudaGetSymbolAddress((void**)&gq,   g_q);
    cudaGetSymbolAddress((void**)&gk,   g_k);
    cudaGetSymbolAddress((void**)&gv,   g_v);
    cudaGetSymbolAddress((void**)&gctx, g_ctx);

    cudaFuncSetAttribute(attn_kernel,
                         cudaFuncAttributeMaxDynamicSharedMemorySize,
                         ATTN_SMEM_BYTES);

    dim3 pg(D_MODEL / 128, M_ROWS / 128);   // (8, 32)
    sgemm_bias<<<pg, 256>>>(query, Wq, bq, gq, 0);
    sgemm_bias<<<pg, 256>>>(key,   Wk, bk, gk, 1);
    sgemm_bias<<<pg, 256>>>(value, Wv, bv, gv, 0);

    attn_kernel<<<dim3(SEQ / 16, BATCH * NH), 256, ATTN_SMEM_BYTES>>>(
        gq, gk, gv, attn, gctx);

    sgemm_bias<<<pg, 256>>>(gctx, Wo, bo, out, 2);
}